// round 3
// baseline (speedup 1.0000x reference)
#include <cuda_runtime.h>

#define B_    2
#define CV_   32
#define D_    24
#define H_    64
#define W_    128
#define NSP   196608          // D*H*W
#define NPB   6291456         // CV*NSP per batch
#define NS_   256
#define FC_   256
#define EPS_  1e-5f

// per-position-block counts
#define ATTN_TPB   128
#define ATTN_BLKS  1536       // NSP / ATTN_TPB
#define RED_BLKS   256

// shared layout of attention kernel (floats)
#define SM_K   0              // [c(16)][n(256)][h(2)]  -> 8192
#define SM_V   8192           // [n(256)][j(16)][h(2)]  -> 8192
#define SM_WQ  16384          // transposed [c][o]      -> 1024
#define SM_WO  17408          // transposed [j][c]      -> 1024
#define SM_RED 18432          // 256 reduction floats
#define SM_FLOATS 18688
#define SMEM_BYTES (SM_FLOATS*4)

// ---------------- scratch (device globals; no runtime allocation) -------------
__device__ float  g_Ki[B_*16*NS_*2];      // [b][c][n][h]
__device__ float  g_Vi[B_*NS_*16*2];      // [b][n][j][h]
__device__ float  g_res[B_*CV_*NSP];      // 50 MB residual buffer
__device__ float2 g_part_in [B_*RED_BLKS];
__device__ float2 g_part_out[B_*ATTN_BLKS];
__device__ float2 g_stats_in [B_];
__device__ float2 g_stats_out[B_];

// ---------------- f32x2 helpers (sm_103a packed math) -------------------------
typedef unsigned long long u64t;

__device__ __forceinline__ u64t ffma2(u64t a, u64t b, u64t c) {
    u64t d; asm("fma.rn.f32x2 %0, %1, %2, %3;" : "=l"(d) : "l"(a), "l"(b), "l"(c)); return d;
}
__device__ __forceinline__ u64t fadd2(u64t a, u64t b) {
    u64t d; asm("add.rn.f32x2 %0, %1, %2;" : "=l"(d) : "l"(a), "l"(b)); return d;
}
__device__ __forceinline__ u64t pk2(float lo, float hi) {
    u64t r; asm("mov.b64 %0, {%1, %2};" : "=l"(r) : "f"(lo), "f"(hi)); return r;
}
__device__ __forceinline__ float2 upk2(u64t v) {
    float2 r; asm("mov.b64 {%0, %1}, %2;" : "=f"(r.x), "=f"(r.y) : "l"(v)); return r;
}
__device__ __forceinline__ float ex2f(float x) {
    float y; asm("ex2.approx.ftz.f32 %0, %1;" : "=f"(y) : "f"(x)); return y;
}

// ---------------- K0: K/V projection (heads interleaved for f32x2) ------------
// grid (64, B), block 256 (thread = token n). Row r<32: K row (h=r>>4,c=r&15);
// r>=32: V row. 256-length dot over feat channels; feat coalesced over n.
__global__ void k_kv(const float* __restrict__ feat,
                     const float* __restrict__ Wk,
                     const float* __restrict__ Wv) {
    int b = blockIdx.y, r = blockIdx.x, n = threadIdx.x;
    const float* fb = feat + (size_t)b * FC_ * NS_ + n;
    float acc = 0.f;
    if (r < 32) {
        const float* wr = Wk + r * FC_;
        #pragma unroll 8
        for (int fc = 0; fc < FC_; fc++) acc += wr[fc] * fb[fc * NS_];
        int h = r >> 4, c = r & 15;
        g_Ki[b * 8192 + c * 512 + n * 2 + h] = acc;
    } else {
        int o = r - 32;
        const float* wr = Wv + o * FC_;
        #pragma unroll 8
        for (int fc = 0; fc < FC_; fc++) acc += wr[fc] * fb[fc * NS_];
        int h = o >> 4, j = o & 15;
        g_Vi[b * 8192 + n * 32 + j * 2 + h] = acc;
    }
}

// ---------------- K1a: gn_in partial reduction (deterministic) ----------------
// grid (256, B), block 256; each block owns a contiguous 24576-float slab.
__global__ void k_reduce_in(const float* __restrict__ cost) {
    int b = blockIdx.y;
    const float4* p = (const float4*)(cost + (size_t)b * NPB);
    int base = blockIdx.x * 6144 + threadIdx.x;
    float s = 0.f, q = 0.f;
    #pragma unroll
    for (int k = 0; k < 24; k++) {
        float4 v = p[base + k * 256];
        s += v.x + v.y + v.z + v.w;
        q += v.x * v.x + v.y * v.y + v.z * v.z + v.w * v.w;
    }
    __shared__ float r[512];
    r[threadIdx.x] = s; r[256 + threadIdx.x] = q;
    __syncthreads();
    for (int st = 128; st > 0; st >>= 1) {
        if (threadIdx.x < st) {
            r[threadIdx.x] += r[threadIdx.x + st];
            r[256 + threadIdx.x] += r[256 + threadIdx.x + st];
        }
        __syncthreads();
    }
    if (threadIdx.x == 0)
        g_part_in[b * RED_BLKS + blockIdx.x] = make_float2(r[0], r[256]);
}

// ---------------- K1b: gn_in finalize -----------------------------------------
__global__ void k_fin_in() {
    __shared__ float r[512];
    for (int b = 0; b < B_; b++) {
        float2 v = g_part_in[b * RED_BLKS + threadIdx.x];
        r[threadIdx.x] = v.x; r[256 + threadIdx.x] = v.y;
        __syncthreads();
        for (int st = 128; st > 0; st >>= 1) {
            if (threadIdx.x < st) {
                r[threadIdx.x] += r[threadIdx.x + st];
                r[256 + threadIdx.x] += r[256 + threadIdx.x + st];
            }
            __syncthreads();
        }
        if (threadIdx.x == 0) {
            float mean = r[0] / (float)NPB;
            float var  = r[256] / (float)NPB - mean * mean;
            g_stats_in[b] = make_float2(mean, rsqrtf(var + EPS_));
        }
        __syncthreads();
    }
}

// ---------------- K2: fused normalize + Qproj + attention + Wo + residual -----
// One thread per spatial position; both heads ride in one f32x2 lane pair.
__global__ void __launch_bounds__(ATTN_TPB, 3)
k_attn(const float* __restrict__ cost,
       const float* __restrict__ Wq,
       const float* __restrict__ Wo,
       const float* __restrict__ giw,
       const float* __restrict__ gib,
       const float* __restrict__ gamma_p) {
    extern __shared__ float sm[];
    int b = blockIdx.y, tid = threadIdx.x;

    for (int i = tid; i < 8192; i += ATTN_TPB) {
        sm[SM_K + i] = g_Ki[b * 8192 + i];
        sm[SM_V + i] = g_Vi[b * 8192 + i];
    }
    for (int i = tid; i < 1024; i += ATTN_TPB) {
        int lo = i & 31, hi = i >> 5;             // transpose both 32x32 mats
        sm[SM_WQ + lo * 32 + hi] = Wq[i];
        sm[SM_WO + lo * 32 + hi] = Wo[i];
    }
    __syncthreads();

    float2 st = g_stats_in[b];
    const float mu = st.x, rstd = st.y;
    int s = blockIdx.x * ATTN_TPB + tid;
    const float* cb = cost + (size_t)b * NPB + s;

    // q = Wq @ groupnorm(cost_col); fold softmax scale * log2(e) into q
    float q[32];
    #pragma unroll
    for (int o = 0; o < 32; o++) q[o] = 0.f;
    #pragma unroll 4
    for (int c = 0; c < 32; c++) {
        float a = (cb[(size_t)c * NSP] - mu) * rstd * giw[c] + gib[c];
        const float* wr = sm + SM_WQ + c * 32;
        #pragma unroll
        for (int o = 0; o < 32; o++) q[o] += a * wr[o];
    }
    const float M = 0.25f * 1.4426950408889634f;   // dqk^-0.5 * log2(e)
    u64t qp[16];
    #pragma unroll
    for (int c = 0; c < 16; c++) qp[c] = pk2(q[c] * M, q[c + 16] * M);

    u64t acc[16];
    #pragma unroll
    for (int j = 0; j < 16; j++) acc[j] = 0ull;
    u64t s2 = 0ull;                                 // (sum_h0, sum_h1)

    #pragma unroll 1
    for (int n = 0; n < NS_; n += 2) {
        u64t l0 = 0ull, l1 = 0ull;                  // (logit_h0, logit_h1) tok n, n+1
        const float* kp = sm + SM_K + n * 2;
        #pragma unroll
        for (int c = 0; c < 16; c++) {
            ulonglong2 kk = *(const ulonglong2*)(kp + c * 512);
            l0 = ffma2(qp[c], kk.x, l0);
            l1 = ffma2(qp[c], kk.y, l1);
        }
        float2 la = upk2(l0), lb = upk2(l1);
        u64t e0 = pk2(ex2f(la.x), ex2f(la.y));
        u64t e1 = pk2(ex2f(lb.x), ex2f(lb.y));
        s2 = fadd2(s2, e0);
        s2 = fadd2(s2, e1);
        const float* vb = sm + SM_V + n * 32;
        #pragma unroll
        for (int j = 0; j < 16; j += 2) {
            ulonglong2 v0 = *(const ulonglong2*)(vb + j * 2);
            ulonglong2 v1 = *(const ulonglong2*)(vb + 32 + j * 2);
            acc[j]     = ffma2(e0, v0.x, acc[j]);
            acc[j + 1] = ffma2(e0, v0.y, acc[j + 1]);
            acc[j]     = ffma2(e1, v1.x, acc[j]);
            acc[j + 1] = ffma2(e1, v1.y, acc[j + 1]);
        }
    }

    // epilogue: normalize by softmax sum, Wo, residual, gn_out partial stats
    float2 ss = upk2(s2);
    float inv0 = 1.0f / ss.x, inv1 = 1.0f / ss.y;
    float ov[32];
    #pragma unroll
    for (int j = 0; j < 16; j++) {
        float2 a = upk2(acc[j]);
        ov[j]      = a.x * inv0;
        ov[16 + j] = a.y * inv1;
    }
    float gamma = *gamma_p;
    float lsum = 0.f, lsq = 0.f;
    #pragma unroll 4
    for (int c = 0; c < 32; c++) {
        float o = 0.f;
        const float* wr = sm + SM_WO;
        #pragma unroll
        for (int j = 0; j < 32; j++) o += ov[j] * wr[j * 32 + c];
        float r = cb[(size_t)c * NSP] + gamma * o;
        g_res[(size_t)(b * CV_ + c) * NSP + s] = r;
        lsum += r; lsq += r * r;
    }
    float* red = sm + SM_RED;
    red[tid] = lsum; red[128 + tid] = lsq;
    __syncthreads();
    for (int stp = 64; stp > 0; stp >>= 1) {
        if (tid < stp) {
            red[tid] += red[tid + stp];
            red[128 + tid] += red[128 + tid + stp];
        }
        __syncthreads();
    }
    if (tid == 0)
        g_part_out[b * ATTN_BLKS + blockIdx.x] = make_float2(red[0], red[128]);
}

// ---------------- K3a: gn_out finalize ----------------------------------------
__global__ void k_fin_out() {
    __shared__ float r[512];
    for (int b = 0; b < B_; b++) {
        float s = 0.f, q = 0.f;
        for (int i = threadIdx.x; i < ATTN_BLKS; i += 256) {
            float2 v = g_part_out[b * ATTN_BLKS + i];
            s += v.x; q += v.y;
        }
        r[threadIdx.x] = s; r[256 + threadIdx.x] = q;
        __syncthreads();
        for (int st = 128; st > 0; st >>= 1) {
            if (threadIdx.x < st) {
                r[threadIdx.x] += r[threadIdx.x + st];
                r[256 + threadIdx.x] += r[256 + threadIdx.x + st];
            }
            __syncthreads();
        }
        if (threadIdx.x == 0) {
            float mean = r[0] / (float)NPB;
            float var  = r[256] / (float)NPB - mean * mean;
            g_stats_out[b] = make_float2(mean, rsqrtf(var + EPS_));
        }
        __syncthreads();
    }
}

// ---------------- K3b: final normalize ----------------------------------------
__global__ void k_norm_out(float* __restrict__ out,
                           const float* __restrict__ w,
                           const float* __restrict__ bb) {
    int g = blockIdx.x * 256 + threadIdx.x;
    const float4* rp = (const float4*)g_res;
    float4* op = (float4*)out;
    for (int i = g; i < (B_ * CV_ * NSP) / 4; i += 3072 * 256) {
        int elem = i * 4;
        int b = elem / NPB;
        int c = (elem - b * NPB) / NSP;
        float2 st = g_stats_out[b];
        float sc = st.y * w[c];
        float off = bb[c] - st.x * sc;
        float4 v = rp[i];
        v.x = v.x * sc + off;
        v.y = v.y * sc + off;
        v.z = v.z * sc + off;
        v.w = v.w * sc + off;
        op[i] = v;
    }
}

// ---------------- launch ------------------------------------------------------
extern "C" void kernel_launch(void* const* d_in, const int* in_sizes, int n_in,
                              void* d_out, int out_size) {
    (void)in_sizes; (void)n_in; (void)out_size;
    const float* cost  = (const float*)d_in[0];
    const float* feat  = (const float*)d_in[1];
    const float* Wq    = (const float*)d_in[2];
    const float* Wk    = (const float*)d_in[3];
    const float* Wv    = (const float*)d_in[4];
    const float* Wo    = (const float*)d_in[5];
    const float* giw   = (const float*)d_in[6];
    const float* gib   = (const float*)d_in[7];
    const float* gow   = (const float*)d_in[8];
    const float* gob   = (const float*)d_in[9];
    const float* gamma = (const float*)d_in[10];
    float* out = (float*)d_out;

    cudaFuncSetAttribute(k_attn, cudaFuncAttributeMaxDynamicSharedMemorySize, SMEM_BYTES);

    k_kv       <<<dim3(64, B_),       256>>>(feat, Wk, Wv);
    k_reduce_in<<<dim3(RED_BLKS, B_), 256>>>(cost);
    k_fin_in   <<<1, 256>>>();
    k_attn     <<<dim3(ATTN_BLKS, B_), ATTN_TPB, SMEM_BYTES>>>(cost, Wq, Wo, giw, gib, gamma);
    k_fin_out  <<<1, 256>>>();
    k_norm_out <<<3072, 256>>>(out, gow, gob);
}

// round 11
// speedup vs baseline: 1.2842x; 1.2842x over previous
#include <cuda_runtime.h>

#define B_    2
#define CV_   32
#define NSP   196608          // D*H*W
#define NPB   6291456         // CV*NSP per batch
#define NS_   256
#define FC_   256
#define EPS_  1e-5f

#define ATTN_TPB   128
#define QPT        2          // queries per thread
#define ATTN_BLKS  768        // NSP / (ATTN_TPB*QPT)
#define RED_BLKS   256

// shared layout of attention kernel (floats)
#define SM_K   0              // [c(16)][n(256)][h(2)]  -> 8192
#define SM_V   8192           // [n(256)][j(16)][h(2)]  -> 8192
#define SM_WQ  16384          // [c(32)][2k+h]          -> 1024
#define SM_WO  17408          // [j'(32)][c(32)]        -> 1024
#define SM_RED 18432          // 256 reduction floats
#define SM_FLOATS 18688
#define SMEM_BYTES (SM_FLOATS*4)

// ---------------- scratch (device globals; no runtime allocation) -------------
__device__ float  g_Ki[B_*16*NS_*2];      // [b][c][n][h]
__device__ float  g_Vi[B_*NS_*16*2];      // [b][n][j][h]
__device__ float  g_res[B_*CV_*NSP];
__device__ float2 g_part_in [B_*RED_BLKS];
__device__ float2 g_part_out[B_*ATTN_BLKS];
__device__ float2 g_stats_in [B_];
__device__ float2 g_stats_out[B_];

// ---------------- f32x2 helpers (sm_103a packed math) -------------------------
typedef unsigned long long u64t;

__device__ __forceinline__ u64t ffma2(u64t a, u64t b, u64t c) {
    u64t d; asm("fma.rn.f32x2 %0, %1, %2, %3;" : "=l"(d) : "l"(a), "l"(b), "l"(c)); return d;
}
__device__ __forceinline__ u64t fadd2(u64t a, u64t b) {
    u64t d; asm("add.rn.f32x2 %0, %1, %2;" : "=l"(d) : "l"(a), "l"(b)); return d;
}
__device__ __forceinline__ u64t pk2(float lo, float hi) {
    u64t r; asm("mov.b64 %0, {%1, %2};" : "=l"(r) : "f"(lo), "f"(hi)); return r;
}
__device__ __forceinline__ float2 upk2(u64t v) {
    float2 r; asm("mov.b64 {%0, %1}, %2;" : "=f"(r.x), "=f"(r.y) : "l"(v)); return r;
}
__device__ __forceinline__ float ex2f(float x) {
    float y; asm("ex2.approx.ftz.f32 %0, %1;" : "=f"(y) : "f"(x)); return y;
}

// ---------------- K0: K/V projection ------------------------------------------
__global__ void k_kv(const float* __restrict__ feat,
                     const float* __restrict__ Wk,
                     const float* __restrict__ Wv) {
    int b = blockIdx.y, r = blockIdx.x, n = threadIdx.x;
    const float* fb = feat + (size_t)b * FC_ * NS_ + n;
    float acc = 0.f;
    if (r < 32) {
        const float* wr = Wk + r * FC_;
        #pragma unroll 8
        for (int fc = 0; fc < FC_; fc++) acc += wr[fc] * fb[fc * NS_];
        int h = r >> 4, c = r & 15;
        g_Ki[b * 8192 + c * 512 + n * 2 + h] = acc;
    } else {
        int o = r - 32;
        const float* wr = Wv + o * FC_;
        #pragma unroll 8
        for (int fc = 0; fc < FC_; fc++) acc += wr[fc] * fb[fc * NS_];
        int h = o >> 4, j = o & 15;
        g_Vi[b * 8192 + n * 32 + j * 2 + h] = acc;
    }
}

// ---------------- K1a: gn_in partial reduction ---------------------------------
__global__ void k_reduce_in(const float* __restrict__ cost) {
    int b = blockIdx.y;
    const float4* p = (const float4*)(cost + (size_t)b * NPB);
    int base = blockIdx.x * 6144 + threadIdx.x;
    float s = 0.f, q = 0.f;
    #pragma unroll
    for (int k = 0; k < 24; k++) {
        float4 v = p[base + k * 256];
        s += v.x + v.y + v.z + v.w;
        q += v.x * v.x + v.y * v.y + v.z * v.z + v.w * v.w;
    }
    __shared__ float r[512];
    r[threadIdx.x] = s; r[256 + threadIdx.x] = q;
    __syncthreads();
    for (int st = 128; st > 0; st >>= 1) {
        if (threadIdx.x < st) {
            r[threadIdx.x] += r[threadIdx.x + st];
            r[256 + threadIdx.x] += r[256 + threadIdx.x + st];
        }
        __syncthreads();
    }
    if (threadIdx.x == 0)
        g_part_in[b * RED_BLKS + blockIdx.x] = make_float2(r[0], r[256]);
}

// ---------------- K1b: gn_in finalize ------------------------------------------
__global__ void k_fin_in() {
    __shared__ float r[512];
    for (int b = 0; b < B_; b++) {
        float2 v = g_part_in[b * RED_BLKS + threadIdx.x];
        r[threadIdx.x] = v.x; r[256 + threadIdx.x] = v.y;
        __syncthreads();
        for (int st = 128; st > 0; st >>= 1) {
            if (threadIdx.x < st) {
                r[threadIdx.x] += r[threadIdx.x + st];
                r[256 + threadIdx.x] += r[256 + threadIdx.x + st];
            }
            __syncthreads();
        }
        if (threadIdx.x == 0) {
            float mean = r[0] / (float)NPB;
            float var  = r[256] / (float)NPB - mean * mean;
            g_stats_in[b] = make_float2(mean, rsqrtf(var + EPS_));
        }
        __syncthreads();
    }
}

// ---------------- K2: fused attention — 2 queries per thread -------------------
__global__ void __launch_bounds__(ATTN_TPB, 3)
k_attn(const float* __restrict__ cost,
       const float* __restrict__ Wq,
       const float* __restrict__ Wo,
       const float* __restrict__ giw,
       const float* __restrict__ gib,
       const float* __restrict__ gamma_p) {
    extern __shared__ float sm[];
    int b = blockIdx.y, tid = threadIdx.x;

    for (int i = tid; i < 8192; i += ATTN_TPB) {
        sm[SM_K + i] = g_Ki[b * 8192 + i];
        sm[SM_V + i] = g_Vi[b * 8192 + i];
    }
    for (int i = tid; i < 1024; i += ATTN_TPB) {
        // WQ: input Wq[o][c], o = h*16+k  ->  sm_WQ[c][2k+h]  (h-interleaved pairs)
        int o = i >> 5, c = i & 31;
        int h = o >> 4, k = o & 15;
        sm[SM_WQ + c * 32 + 2 * k + h] = Wq[i];
        // WO: input Wo[c][j'] -> sm_WO[j'][c]
        int jp = i & 31, cc = i >> 5;
        sm[SM_WO + jp * 32 + cc] = Wo[i];
    }
    __syncthreads();

    float2 st = g_stats_in[b];
    const float mu = st.x, rstd = st.y;
    int s0 = blockIdx.x * (ATTN_TPB * QPT) + tid;      // query A; query B = s0+128
    const float* cbA = cost + (size_t)b * NPB + s0;

    // ---- Q projection, f32x2 over (h0,h1) pairs; scale folded into activation
    const float M = 0.25f * 1.4426950408889634f;       // dqk^-0.5 * log2(e)
    u64t qpA[16], qpB[16];
    #pragma unroll
    for (int k = 0; k < 16; k++) { qpA[k] = 0ull; qpB[k] = 0ull; }
    #pragma unroll 4
    for (int c = 0; c < 32; c++) {
        float gw = giw[c] * rstd, gbias = gib[c] - mu * rstd * giw[c];
        float aA = (cbA[(size_t)c * NSP] * gw + gbias) * M;
        float aB = (cbA[(size_t)c * NSP + ATTN_TPB] * gw + gbias) * M;
        u64t a2A = pk2(aA, aA), a2B = pk2(aB, aB);
        const u64t* w2 = (const u64t*)(sm + SM_WQ + c * 32);
        #pragma unroll
        for (int k = 0; k < 16; k++) {
            u64t w = w2[k];
            qpA[k] = ffma2(a2A, w, qpA[k]);
            qpB[k] = ffma2(a2B, w, qpB[k]);
        }
    }

    u64t accA[16], accB[16];
    #pragma unroll
    for (int j = 0; j < 16; j++) { accA[j] = 0ull; accB[j] = 0ull; }
    u64t sA = 0ull, sB = 0ull;

    #pragma unroll 1
    for (int n = 0; n < NS_; n += 2) {
        u64t lA0 = 0ull, lA1 = 0ull, lB0 = 0ull, lB1 = 0ull;
        #pragma unroll
        for (int c = 0; c < 16; c++) {
            ulonglong2 kk = *(const ulonglong2*)(sm + SM_K + c * 512 + n * 2);
            lA0 = ffma2(qpA[c], kk.x, lA0);
            lA1 = ffma2(qpA[c], kk.y, lA1);
            lB0 = ffma2(qpB[c], kk.x, lB0);
            lB1 = ffma2(qpB[c], kk.y, lB1);
        }
        float2 a0 = upk2(lA0), a1 = upk2(lA1), b0 = upk2(lB0), b1 = upk2(lB1);
        u64t eA0 = pk2(ex2f(a0.x), ex2f(a0.y));
        u64t eA1 = pk2(ex2f(a1.x), ex2f(a1.y));
        u64t eB0 = pk2(ex2f(b0.x), ex2f(b0.y));
        u64t eB1 = pk2(ex2f(b1.x), ex2f(b1.y));
        sA = fadd2(sA, eA0); sA = fadd2(sA, eA1);
        sB = fadd2(sB, eB0); sB = fadd2(sB, eB1);
        const float* vb = sm + SM_V + n * 32;
        #pragma unroll
        for (int j = 0; j < 16; j += 2) {
            ulonglong2 v0 = *(const ulonglong2*)(vb + j * 2);
            ulonglong2 v1 = *(const ulonglong2*)(vb + 32 + j * 2);
            accA[j]     = ffma2(eA0, v0.x, accA[j]);
            accA[j + 1] = ffma2(eA0, v0.y, accA[j + 1]);
            accA[j]     = ffma2(eA1, v1.x, accA[j]);
            accA[j + 1] = ffma2(eA1, v1.y, accA[j + 1]);
            accB[j]     = ffma2(eB0, v0.x, accB[j]);
            accB[j + 1] = ffma2(eB0, v0.y, accB[j + 1]);
            accB[j]     = ffma2(eB1, v1.x, accB[j]);
            accB[j + 1] = ffma2(eB1, v1.y, accB[j + 1]);
        }
    }

    // ---- epilogue: softmax normalize, Wo (f32x2 over c-pairs), residual, stats
    float2 ssA = upk2(sA), ssB = upk2(sB);
    float iA0 = 1.0f / ssA.x, iA1 = 1.0f / ssA.y;
    float iB0 = 1.0f / ssB.x, iB1 = 1.0f / ssB.y;
    float ovA[32], ovB[32];
    #pragma unroll
    for (int j = 0; j < 16; j++) {
        float2 a = upk2(accA[j]); ovA[j] = a.x * iA0; ovA[16 + j] = a.y * iA1;
        float2 e = upk2(accB[j]); ovB[j] = e.x * iB0; ovB[16 + j] = e.y * iB1;
    }
    u64t oA2[16], oB2[16];
    #pragma unroll
    for (int c2 = 0; c2 < 16; c2++) { oA2[c2] = 0ull; oB2[c2] = 0ull; }
    #pragma unroll 4
    for (int jp = 0; jp < 32; jp++) {
        u64t vA = pk2(ovA[jp], ovA[jp]), vB = pk2(ovB[jp], ovB[jp]);
        const u64t* w = (const u64t*)(sm + SM_WO + jp * 32);
        #pragma unroll
        for (int c2 = 0; c2 < 16; c2++) {
            u64t ww = w[c2];
            oA2[c2] = ffma2(vA, ww, oA2[c2]);
            oB2[c2] = ffma2(vB, ww, oB2[c2]);
        }
    }
    float gamma = *gamma_p;
    float lsum = 0.f, lsq = 0.f;
    #pragma unroll 4
    for (int c2 = 0; c2 < 16; c2++) {
        float2 oa = upk2(oA2[c2]), ob = upk2(oB2[c2]);
        int c = 2 * c2;
        float rA0 = cbA[(size_t)c * NSP] + gamma * oa.x;
        float rA1 = cbA[(size_t)(c + 1) * NSP] + gamma * oa.y;
        float rB0 = cbA[(size_t)c * NSP + ATTN_TPB] + gamma * ob.x;
        float rB1 = cbA[(size_t)(c + 1) * NSP + ATTN_TPB] + gamma * ob.y;
        size_t base = (size_t)(b * CV_ + c) * NSP + s0;
        g_res[base] = rA0;
        g_res[base + NSP] = rA1;
        g_res[base + ATTN_TPB] = rB0;
        g_res[base + NSP + ATTN_TPB] = rB1;
        lsum += rA0 + rA1 + rB0 + rB1;
        lsq  += rA0 * rA0 + rA1 * rA1 + rB0 * rB0 + rB1 * rB1;
    }
    float* red = sm + SM_RED;
    red[tid] = lsum; red[128 + tid] = lsq;
    __syncthreads();
    for (int stp = 64; stp > 0; stp >>= 1) {
        if (tid < stp) {
            red[tid] += red[tid + stp];
            red[128 + tid] += red[128 + tid + stp];
        }
        __syncthreads();
    }
    if (tid == 0)
        g_part_out[b * ATTN_BLKS + blockIdx.x] = make_float2(red[0], red[128]);
}

// ---------------- K3a: gn_out finalize -----------------------------------------
__global__ void k_fin_out() {
    __shared__ float r[512];
    for (int b = 0; b < B_; b++) {
        float s = 0.f, q = 0.f;
        for (int i = threadIdx.x; i < ATTN_BLKS; i += 256) {
            float2 v = g_part_out[b * ATTN_BLKS + i];
            s += v.x; q += v.y;
        }
        r[threadIdx.x] = s; r[256 + threadIdx.x] = q;
        __syncthreads();
        for (int st = 128; st > 0; st >>= 1) {
            if (threadIdx.x < st) {
                r[threadIdx.x] += r[threadIdx.x + st];
                r[256 + threadIdx.x] += r[256 + threadIdx.x + st];
            }
            __syncthreads();
        }
        if (threadIdx.x == 0) {
            float mean = r[0] / (float)NPB;
            float var  = r[256] / (float)NPB - mean * mean;
            g_stats_out[b] = make_float2(mean, rsqrtf(var + EPS_));
        }
        __syncthreads();
    }
}

// ---------------- K3b: final normalize -----------------------------------------
__global__ void k_norm_out(float* __restrict__ out,
                           const float* __restrict__ w,
                           const float* __restrict__ bb) {
    int g = blockIdx.x * 256 + threadIdx.x;
    const float4* rp = (const float4*)g_res;
    float4* op = (float4*)out;
    for (int i = g; i < (B_ * CV_ * NSP) / 4; i += 3072 * 256) {
        int elem = i * 4;
        int b = elem / NPB;
        int c = (elem - b * NPB) / NSP;
        float2 st = g_stats_out[b];
        float sc = st.y * w[c];
        float off = bb[c] - st.x * sc;
        float4 v = rp[i];
        v.x = v.x * sc + off;
        v.y = v.y * sc + off;
        v.z = v.z * sc + off;
        v.w = v.w * sc + off;
        op[i] = v;
    }
}

// ---------------- launch -------------------------------------------------------
extern "C" void kernel_launch(void* const* d_in, const int* in_sizes, int n_in,
                              void* d_out, int out_size) {
    (void)in_sizes; (void)n_in; (void)out_size;
    const float* cost  = (const float*)d_in[0];
    const float* feat  = (const float*)d_in[1];
    const float* Wq    = (const float*)d_in[2];
    const float* Wk    = (const float*)d_in[3];
    const float* Wv    = (const float*)d_in[4];
    const float* Wo    = (const float*)d_in[5];
    const float* giw   = (const float*)d_in[6];
    const float* gib   = (const float*)d_in[7];
    const float* gow   = (const float*)d_in[8];
    const float* gob   = (const float*)d_in[9];
    const float* gamma = (const float*)d_in[10];
    float* out = (float*)d_out;

    cudaFuncSetAttribute(k_attn, cudaFuncAttributeMaxDynamicSharedMemorySize, SMEM_BYTES);

    k_kv       <<<dim3(64, B_),       256>>>(feat, Wk, Wv);
    k_reduce_in<<<dim3(RED_BLKS, B_), 256>>>(cost);
    k_fin_in   <<<1, 256>>>();
    k_attn     <<<dim3(ATTN_BLKS, B_), ATTN_TPB, SMEM_BYTES>>>(cost, Wq, Wo, giw, gib, gamma);
    k_fin_out  <<<1, 256>>>();
    k_norm_out <<<3072, 256>>>(out, gow, gob);
}

// round 12
// speedup vs baseline: 1.3441x; 1.0466x over previous
#include <cuda_runtime.h>

#define B_    2
#define CV_   32
#define NSP   196608          // D*H*W
#define NPB   6291456         // CV*NSP per batch
#define NS_   256
#define FC_   256
#define EPS_  1e-5f

#define ATTN_TPB   128
#define QPT        2          // queries per thread
#define ATTN_BLKS  768        // NSP / (ATTN_TPB*QPT)
#define RED_BLKS   256

// shared layout of attention kernel (floats)
#define SM_K   0              // [c(16)][n(256)][h(2)]  -> 8192
#define SM_V   8192           // [n(256)][j(16)][h(2)]  -> 8192
#define SM_WQ  16384          // [c(32)][2k+h]          -> 1024
#define SM_WO  17408          // [j'(32)][c(32)]        -> 1024
#define SM_RED 18432          // 256 reduction floats
#define SM_FLOATS 18688
#define SMEM_BYTES (SM_FLOATS*4)

// ---------------- scratch (device globals; no runtime allocation) -------------
__device__ float  g_Ki[B_*16*NS_*2];      // [b][c][n][h]
__device__ float  g_Vi[B_*NS_*16*2];      // [b][n][j][h]
__device__ float  g_res[B_*CV_*NSP];
__device__ float2 g_part_in [B_*RED_BLKS];
__device__ float2 g_part_out[B_*ATTN_BLKS];
__device__ float2 g_stats_in [B_];
__device__ float2 g_stats_out[B_];

// ---------------- f32x2 helpers (sm_103a packed math) -------------------------
typedef unsigned long long u64t;

__device__ __forceinline__ u64t ffma2(u64t a, u64t b, u64t c) {
    u64t d; asm("fma.rn.f32x2 %0, %1, %2, %3;" : "=l"(d) : "l"(a), "l"(b), "l"(c)); return d;
}
__device__ __forceinline__ u64t fadd2(u64t a, u64t b) {
    u64t d; asm("add.rn.f32x2 %0, %1, %2;" : "=l"(d) : "l"(a), "l"(b)); return d;
}
__device__ __forceinline__ u64t pk2(float lo, float hi) {
    u64t r; asm("mov.b64 %0, {%1, %2};" : "=l"(r) : "f"(lo), "f"(hi)); return r;
}
__device__ __forceinline__ float2 upk2(u64t v) {
    float2 r; asm("mov.b64 {%0, %1}, %2;" : "=f"(r.x), "=f"(r.y) : "l"(v)); return r;
}
__device__ __forceinline__ float ex2f(float x) {
    float y; asm("ex2.approx.ftz.f32 %0, %1;" : "=f"(y) : "f"(x)); return y;
}

// ---------------- K0: K/V projection ------------------------------------------
__global__ void k_kv(const float* __restrict__ feat,
                     const float* __restrict__ Wk,
                     const float* __restrict__ Wv) {
    int b = blockIdx.y, r = blockIdx.x, n = threadIdx.x;
    const float* fb = feat + (size_t)b * FC_ * NS_ + n;
    float acc = 0.f;
    if (r < 32) {
        const float* wr = Wk + r * FC_;
        #pragma unroll 8
        for (int fc = 0; fc < FC_; fc++) acc += wr[fc] * fb[fc * NS_];
        int h = r >> 4, c = r & 15;
        g_Ki[b * 8192 + c * 512 + n * 2 + h] = acc;
    } else {
        int o = r - 32;
        const float* wr = Wv + o * FC_;
        #pragma unroll 8
        for (int fc = 0; fc < FC_; fc++) acc += wr[fc] * fb[fc * NS_];
        int h = o >> 4, j = o & 15;
        g_Vi[b * 8192 + n * 32 + j * 2 + h] = acc;
    }
}

// ---------------- K1a: gn_in partial reduction ---------------------------------
__global__ void k_reduce_in(const float* __restrict__ cost) {
    int b = blockIdx.y;
    const float4* p = (const float4*)(cost + (size_t)b * NPB);
    int base = blockIdx.x * 6144 + threadIdx.x;
    float s = 0.f, q = 0.f;
    #pragma unroll
    for (int k = 0; k < 24; k++) {
        float4 v = p[base + k * 256];
        s += v.x + v.y + v.z + v.w;
        q += v.x * v.x + v.y * v.y + v.z * v.z + v.w * v.w;
    }
    __shared__ float r[512];
    r[threadIdx.x] = s; r[256 + threadIdx.x] = q;
    __syncthreads();
    for (int st = 128; st > 0; st >>= 1) {
        if (threadIdx.x < st) {
            r[threadIdx.x] += r[threadIdx.x + st];
            r[256 + threadIdx.x] += r[256 + threadIdx.x + st];
        }
        __syncthreads();
    }
    if (threadIdx.x == 0)
        g_part_in[b * RED_BLKS + blockIdx.x] = make_float2(r[0], r[256]);
}

// ---------------- K1b: gn_in finalize ------------------------------------------
__global__ void k_fin_in() {
    __shared__ float r[512];
    for (int b = 0; b < B_; b++) {
        float2 v = g_part_in[b * RED_BLKS + threadIdx.x];
        r[threadIdx.x] = v.x; r[256 + threadIdx.x] = v.y;
        __syncthreads();
        for (int st = 128; st > 0; st >>= 1) {
            if (threadIdx.x < st) {
                r[threadIdx.x] += r[threadIdx.x + st];
                r[256 + threadIdx.x] += r[256 + threadIdx.x + st];
            }
            __syncthreads();
        }
        if (threadIdx.x == 0) {
            float mean = r[0] / (float)NPB;
            float var  = r[256] / (float)NPB - mean * mean;
            g_stats_in[b] = make_float2(mean, rsqrtf(var + EPS_));
        }
        __syncthreads();
    }
}

// ---------------- K2: fused attention — 2 queries/thread, 4 tokens/iter --------
__global__ void __launch_bounds__(ATTN_TPB, 2)
k_attn(const float* __restrict__ cost,
       const float* __restrict__ Wq,
       const float* __restrict__ Wo,
       const float* __restrict__ giw,
       const float* __restrict__ gib,
       const float* __restrict__ gamma_p) {
    extern __shared__ float sm[];
    int b = blockIdx.y, tid = threadIdx.x;

    for (int i = tid; i < 8192; i += ATTN_TPB) {
        sm[SM_K + i] = g_Ki[b * 8192 + i];
        sm[SM_V + i] = g_Vi[b * 8192 + i];
    }
    for (int i = tid; i < 1024; i += ATTN_TPB) {
        // WQ: input Wq[o][c], o = h*16+k  ->  sm_WQ[c][2k+h]  (h-interleaved pairs)
        int o = i >> 5, c = i & 31;
        int h = o >> 4, k = o & 15;
        sm[SM_WQ + c * 32 + 2 * k + h] = Wq[i];
        // WO: input Wo[c][j'] -> sm_WO[j'][c]
        int jp = i & 31, cc = i >> 5;
        sm[SM_WO + jp * 32 + cc] = Wo[i];
    }
    __syncthreads();

    float2 st = g_stats_in[b];
    const float mu = st.x, rstd = st.y;
    int s0 = blockIdx.x * (ATTN_TPB * QPT) + tid;      // query A; query B = s0+128
    const float* cbA = cost + (size_t)b * NPB + s0;

    // ---- Q projection, f32x2 over (h0,h1) pairs; scale folded into activation
    const float M = 0.25f * 1.4426950408889634f;       // dqk^-0.5 * log2(e)
    u64t qpA[16], qpB[16];
    #pragma unroll
    for (int k = 0; k < 16; k++) { qpA[k] = 0ull; qpB[k] = 0ull; }
    #pragma unroll 4
    for (int c = 0; c < 32; c++) {
        float gw = giw[c] * rstd, gbias = gib[c] - mu * rstd * giw[c];
        float aA = (cbA[(size_t)c * NSP] * gw + gbias) * M;
        float aB = (cbA[(size_t)c * NSP + ATTN_TPB] * gw + gbias) * M;
        u64t a2A = pk2(aA, aA), a2B = pk2(aB, aB);
        const u64t* w2 = (const u64t*)(sm + SM_WQ + c * 32);
        #pragma unroll
        for (int k = 0; k < 16; k++) {
            u64t w = w2[k];
            qpA[k] = ffma2(a2A, w, qpA[k]);
            qpB[k] = ffma2(a2B, w, qpB[k]);
        }
    }

    u64t accA[16], accB[16];
    #pragma unroll
    for (int j = 0; j < 16; j++) { accA[j] = 0ull; accB[j] = 0ull; }
    u64t sA = 0ull, sB = 0ull;

    // 4 tokens per iteration: 8 independent logit chains, batched ex2,
    // cross-block ILP for the schedulers (2 CTAs/SM -> 256-reg budget).
    #pragma unroll 1
    for (int n = 0; n < NS_; n += 4) {
        u64t l[8];
        #pragma unroll
        for (int i = 0; i < 8; i++) l[i] = 0ull;
        #pragma unroll
        for (int c = 0; c < 16; c++) {
            const float* kp = sm + SM_K + c * 512 + n * 2;
            ulonglong2 k01 = *(const ulonglong2*)(kp);
            ulonglong2 k23 = *(const ulonglong2*)(kp + 4);
            l[0] = ffma2(qpA[c], k01.x, l[0]);
            l[1] = ffma2(qpA[c], k01.y, l[1]);
            l[2] = ffma2(qpA[c], k23.x, l[2]);
            l[3] = ffma2(qpA[c], k23.y, l[3]);
            l[4] = ffma2(qpB[c], k01.x, l[4]);
            l[5] = ffma2(qpB[c], k01.y, l[5]);
            l[6] = ffma2(qpB[c], k23.x, l[6]);
            l[7] = ffma2(qpB[c], k23.y, l[7]);
        }
        u64t e[8];
        #pragma unroll
        for (int i = 0; i < 8; i++) {
            float2 f = upk2(l[i]);
            e[i] = pk2(ex2f(f.x), ex2f(f.y));
        }
        // tree-reduced softmax-sum update (4-cyc loop-carried chain)
        sA = fadd2(sA, fadd2(fadd2(e[0], e[1]), fadd2(e[2], e[3])));
        sB = fadd2(sB, fadd2(fadd2(e[4], e[5]), fadd2(e[6], e[7])));
        #pragma unroll
        for (int t = 0; t < 4; t++) {
            const float* vb = sm + SM_V + (n + t) * 32;
            u64t ea = e[t], eb = e[4 + t];
            #pragma unroll
            for (int j = 0; j < 16; j += 2) {
                ulonglong2 v = *(const ulonglong2*)(vb + j * 2);
                accA[j]     = ffma2(ea, v.x, accA[j]);
                accA[j + 1] = ffma2(ea, v.y, accA[j + 1]);
                accB[j]     = ffma2(eb, v.x, accB[j]);
                accB[j + 1] = ffma2(eb, v.y, accB[j + 1]);
            }
        }
    }

    // ---- epilogue: softmax normalize, Wo (f32x2 over c-pairs), residual, stats
    float2 ssA = upk2(sA), ssB = upk2(sB);
    float iA0 = 1.0f / ssA.x, iA1 = 1.0f / ssA.y;
    float iB0 = 1.0f / ssB.x, iB1 = 1.0f / ssB.y;
    float ovA[32], ovB[32];
    #pragma unroll
    for (int j = 0; j < 16; j++) {
        float2 a = upk2(accA[j]); ovA[j] = a.x * iA0; ovA[16 + j] = a.y * iA1;
        float2 e2 = upk2(accB[j]); ovB[j] = e2.x * iB0; ovB[16 + j] = e2.y * iB1;
    }
    u64t oA2[16], oB2[16];
    #pragma unroll
    for (int c2 = 0; c2 < 16; c2++) { oA2[c2] = 0ull; oB2[c2] = 0ull; }
    #pragma unroll 4
    for (int jp = 0; jp < 32; jp++) {
        u64t vA = pk2(ovA[jp], ovA[jp]), vB = pk2(ovB[jp], ovB[jp]);
        const u64t* w = (const u64t*)(sm + SM_WO + jp * 32);
        #pragma unroll
        for (int c2 = 0; c2 < 16; c2++) {
            u64t ww = w[c2];
            oA2[c2] = ffma2(vA, ww, oA2[c2]);
            oB2[c2] = ffma2(vB, ww, oB2[c2]);
        }
    }
    float gamma = *gamma_p;
    float lsum = 0.f, lsq = 0.f;
    #pragma unroll 4
    for (int c2 = 0; c2 < 16; c2++) {
        float2 oa = upk2(oA2[c2]), ob = upk2(oB2[c2]);
        int c = 2 * c2;
        float rA0 = cbA[(size_t)c * NSP] + gamma * oa.x;
        float rA1 = cbA[(size_t)(c + 1) * NSP] + gamma * oa.y;
        float rB0 = cbA[(size_t)c * NSP + ATTN_TPB] + gamma * ob.x;
        float rB1 = cbA[(size_t)(c + 1) * NSP + ATTN_TPB] + gamma * ob.y;
        size_t base = (size_t)(b * CV_ + c) * NSP + s0;
        g_res[base] = rA0;
        g_res[base + NSP] = rA1;
        g_res[base + ATTN_TPB] = rB0;
        g_res[base + NSP + ATTN_TPB] = rB1;
        lsum += rA0 + rA1 + rB0 + rB1;
        lsq  += rA0 * rA0 + rA1 * rA1 + rB0 * rB0 + rB1 * rB1;
    }
    float* red = sm + SM_RED;
    red[tid] = lsum; red[128 + tid] = lsq;
    __syncthreads();
    for (int stp = 64; stp > 0; stp >>= 1) {
        if (tid < stp) {
            red[tid] += red[tid + stp];
            red[128 + tid] += red[128 + tid + stp];
        }
        __syncthreads();
    }
    if (tid == 0)
        g_part_out[b * ATTN_BLKS + blockIdx.x] = make_float2(red[0], red[128]);
}

// ---------------- K3a: gn_out finalize -----------------------------------------
__global__ void k_fin_out() {
    __shared__ float r[512];
    for (int b = 0; b < B_; b++) {
        float s = 0.f, q = 0.f;
        for (int i = threadIdx.x; i < ATTN_BLKS; i += 256) {
            float2 v = g_part_out[b * ATTN_BLKS + i];
            s += v.x; q += v.y;
        }
        r[threadIdx.x] = s; r[256 + threadIdx.x] = q;
        __syncthreads();
        for (int st = 128; st > 0; st >>= 1) {
            if (threadIdx.x < st) {
                r[threadIdx.x] += r[threadIdx.x + st];
                r[256 + threadIdx.x] += r[256 + threadIdx.x + st];
            }
            __syncthreads();
        }
        if (threadIdx.x == 0) {
            float mean = r[0] / (float)NPB;
            float var  = r[256] / (float)NPB - mean * mean;
            g_stats_out[b] = make_float2(mean, rsqrtf(var + EPS_));
        }
        __syncthreads();
    }
}

// ---------------- K3b: final normalize -----------------------------------------
__global__ void k_norm_out(float* __restrict__ out,
                           const float* __restrict__ w,
                           const float* __restrict__ bb) {
    int g = blockIdx.x * 256 + threadIdx.x;
    const float4* rp = (const float4*)g_res;
    float4* op = (float4*)out;
    for (int i = g; i < (B_ * CV_ * NSP) / 4; i += 3072 * 256) {
        int elem = i * 4;
        int b = elem / NPB;
        int c = (elem - b * NPB) / NSP;
        float2 st = g_stats_out[b];
        float sc = st.y * w[c];
        float off = bb[c] - st.x * sc;
        float4 v = rp[i];
        v.x = v.x * sc + off;
        v.y = v.y * sc + off;
        v.z = v.z * sc + off;
        v.w = v.w * sc + off;
        op[i] = v;
    }
}

// ---------------- launch -------------------------------------------------------
extern "C" void kernel_launch(void* const* d_in, const int* in_sizes, int n_in,
                              void* d_out, int out_size) {
    (void)in_sizes; (void)n_in; (void)out_size;
    const float* cost  = (const float*)d_in[0];
    const float* feat  = (const float*)d_in[1];
    const float* Wq    = (const float*)d_in[2];
    const float* Wk    = (const float*)d_in[3];
    const float* Wv    = (const float*)d_in[4];
    const float* Wo    = (const float*)d_in[5];
    const float* giw   = (const float*)d_in[6];
    const float* gib   = (const float*)d_in[7];
    const float* gow   = (const float*)d_in[8];
    const float* gob   = (const float*)d_in[9];
    const float* gamma = (const float*)d_in[10];
    float* out = (float*)d_out;

    cudaFuncSetAttribute(k_attn, cudaFuncAttributeMaxDynamicSharedMemorySize, SMEM_BYTES);

    k_kv       <<<dim3(64, B_),       256>>>(feat, Wk, Wv);
    k_reduce_in<<<dim3(RED_BLKS, B_), 256>>>(cost);
    k_fin_in   <<<1, 256>>>();
    k_attn     <<<dim3(ATTN_BLKS, B_), ATTN_TPB, SMEM_BYTES>>>(cost, Wq, Wo, giw, gib, gamma);
    k_fin_out  <<<1, 256>>>();
    k_norm_out <<<3072, 256>>>(out, gow, gob);
}